// round 3
// baseline (speedup 1.0000x reference)
#include <cuda_runtime.h>
#include <cuda_bf16.h>

// LSTMHierarchialAttention2 — constant-folded output (see R1/R2 notes):
// softmax over a singleton axis == 1.0f exactly, so the entire LSTM/
// attention hierarchy is dead code. Correct output = single fp32 1.0.
//
// R2 converged the kernel-node path to the dispatch floor (4.61 us,
// ncu kernel dur ~3.3 us, all pipes 0%). This round probes whether a
// graph MEMCPY node (4-byte D2D from a module-scope __device__ constant)
// replays cheaper than a kernel node. No allocation: the source lives in
// the module's device image.

__device__ float d_one_const = 1.0f;  // module-load initialized, no cudaMalloc

// Fallback kernel kept for the padded-out_size safety net.
__global__ void write_one_n_kernel(float* __restrict__ out, int n) {
    int i = blockIdx.x * blockDim.x + threadIdx.x;
    if (i < n) out[i] = 1.0f;
}

extern "C" void kernel_launch(void* const* d_in, const int* in_sizes, int n_in,
                              void* d_out, int out_size) {
    (void)d_in; (void)in_sizes; (void)n_in;
    float* out = (float*)d_out;

    if (out_size == 1) {
        // 4-byte D2D memcpy node: src is the device-image constant.
        // cudaGetSymbolAddress is a query (no stream work) — capture-safe.
        void* src = nullptr;
        cudaGetSymbolAddress(&src, d_one_const);
        cudaMemcpyAsync(out, src, sizeof(float), cudaMemcpyDeviceToDevice, 0);
    } else {
        int threads = 128;
        int blocks = (out_size + threads - 1) / threads;
        write_one_n_kernel<<<blocks, threads>>>(out, out_size);
    }
}

// round 4
// speedup vs baseline: 1.0556x; 1.0556x over previous
#include <cuda_runtime.h>
#include <cuda_bf16.h>

// LSTMHierarchialAttention2 — constant-folded output.
//
// Reference ends with softmax over a singleton axis:
//     logits = doc @ Wf.T + bf            # shape (1, 1)
//     return jax.nn.softmax(logits, axis=1)   # == 1.0f exactly
//
// e^x / e^x == 1.0f for any finite fp32 x, so both LSTM scans, both
// attention blocks, and the final linear are dead code w.r.t. the output.
//
// Floor-probe history:
//   R1  <<<1,32>>> + bounds check : 4.86 us
//   R2  <<<1,1>>>  single STG     : 4.61 us  <- best (kernel-node floor)
//   R3  4B D2D memcpy graph node  : 4.86 us  (CE/memcpy node not cheaper)
// All ncu pipes 0%; kernel dur pinned ~3.3 us regardless of body — this is
// GB300 graph-node dispatch overhead, not instruction time. Reverting to R2.

__global__ void __launch_bounds__(1) write_one_kernel(float* __restrict__ out) {
    *out = 1.0f;
}

__global__ void write_one_n_kernel(float* __restrict__ out, int n) {
    int i = blockIdx.x * blockDim.x + threadIdx.x;
    if (i < n) out[i] = 1.0f;
}

extern "C" void kernel_launch(void* const* d_in, const int* in_sizes, int n_in,
                              void* d_out, int out_size) {
    (void)d_in; (void)in_sizes; (void)n_in;
    float* out = (float*)d_out;
    if (out_size == 1) {
        // Actual case: output shape (1,1) fp32 — one unconditional store.
        write_one_kernel<<<1, 1>>>(out);
    } else {
        // Safety net for padded out_size.
        int threads = 128;
        int blocks = (out_size + threads - 1) / threads;
        write_one_n_kernel<<<blocks, threads>>>(out, out_size);
    }
}